// round 11
// baseline (speedup 1.0000x reference)
#include <cuda_runtime.h>
#include <cuda_bf16.h>
#include <math.h>
#include <stdint.h>

#define BATCH 8
#define CH    128
#define NT    4096
#define NF    2049
#define FPAD  2064
#define FT    2176          /* padded F for tensor path: 17*128 */
#define SQRTN 64.0f
#define ATT_SCALE 0.08838834764831845f  /* 1/sqrt(128) */

#if defined(__CUDA_ARCH_FEAT_SM103_ALL) || defined(__CUDA_ARCH_FEAT_SM100_ALL)
#define TC_ENABLED 1
#else
#define TC_ENABLED 0
#endif

// ---------------- scratch ------------------------------------------------------
__device__ float g_Xr[BATCH*CH*FPAD];
__device__ float g_Xi[BATCH*CH*FPAD];
__device__ float g_Or[BATCH*CH*FPAD];
__device__ float g_Oi[BATCH*CH*FPAD];
__device__ float g_energy[BATCH*NF];
__device__ float g_normv[BATCH*NF];
__device__ float g_med[BATCH];
__device__ float g_thr[1];
__device__ float2 g_tw[4096];
__device__ float g_lsum[BATCH*FT];     /* row sums of e (atomic) */

#define QKN ((size_t)BATCH*FT*CH)     /* [b][f][c] */
#define VN  ((size_t)BATCH*CH*FT)     /* [b][c][g] */
#define PN  ((size_t)BATCH*FT*FT)     /* [b][f][g] */
__device__ __align__(256) __nv_bfloat16 g_qrh[QKN], g_qrl[QKN];
__device__ __align__(256) __nv_bfloat16 g_qih[QKN], g_qil[QKN];
__device__ __align__(256) __nv_bfloat16 g_krh[QKN], g_krl[QKN];
__device__ __align__(256) __nv_bfloat16 g_kih[QKN], g_kil[QKN];
__device__ __align__(256) __nv_bfloat16 g_vrh[VN],  g_vrl[VN];
__device__ __align__(256) __nv_bfloat16 g_vih[VN],  g_vil[VN];
__device__ __align__(256) __nv_bfloat16 g_wkh[CH*CH], g_wkl[CH*CH];
__device__ __align__(256) __nv_bfloat16 g_wvh[CH*CH], g_wvl[CH*CH];
__device__ __align__(256) float g_S[PN];   /* e = exp(|S|*scale) */

// ================= tcgen05 helpers (feature-gated) ============================
__device__ __forceinline__ uint32_t smem_u32(const void* p) {
    uint32_t a;
    asm("{ .reg .u64 t; cvta.to.shared.u64 t, %1; cvt.u32.u64 %0, t; }" : "=r"(a) : "l"(p));
    return a;
}
__device__ __forceinline__ uint32_t elect_one() {
    uint32_t p;
    asm volatile("{ .reg .pred p; elect.sync _|p, 0xFFFFFFFF; selp.b32 %0, 1, 0, p; }" : "=r"(p));
    return p;
}
__device__ __forceinline__ void tc_alloc(uint32_t sa, uint32_t n) {
#if TC_ENABLED
    asm volatile("tcgen05.alloc.cta_group::1.sync.aligned.shared::cta.b32 [%0], %1;" :: "r"(sa), "r"(n) : "memory");
#endif
}
__device__ __forceinline__ void tc_dealloc(uint32_t tm, uint32_t n) {
#if TC_ENABLED
    asm volatile("tcgen05.dealloc.cta_group::1.sync.aligned.b32 %0, %1;" :: "r"(tm), "r"(n));
#endif
}
__device__ __forceinline__ void tc_commit(uint32_t mb) {
#if TC_ENABLED
    asm volatile("tcgen05.commit.cta_group::1.mbarrier::arrive::one.shared::cluster.b64 [%0];" :: "r"(mb) : "memory");
#endif
}
__device__ __forceinline__ void tc_wait_ld() {
#if TC_ENABLED
    asm volatile("tcgen05.wait::ld.sync.aligned;" ::: "memory");
#endif
}
__device__ __forceinline__ void tc_fence_after() {
#if TC_ENABLED
    asm volatile("tcgen05.fence::after_thread_sync;" ::: "memory");
#endif
}
__device__ __forceinline__ void tc_ld_x32(uint32_t* r, uint32_t ta) {
#if TC_ENABLED
    asm volatile("tcgen05.ld.sync.aligned.32x32b.x32.b32 "
        "{%0, %1, %2, %3, %4, %5, %6, %7, %8, %9, %10, %11, %12, %13, %14, %15, "
        " %16, %17, %18, %19, %20, %21, %22, %23, %24, %25, %26, %27, %28, %29, %30, %31}, [%32];"
        : "=r"(r[0]),  "=r"(r[1]),  "=r"(r[2]),  "=r"(r[3]),
          "=r"(r[4]),  "=r"(r[5]),  "=r"(r[6]),  "=r"(r[7]),
          "=r"(r[8]),  "=r"(r[9]),  "=r"(r[10]), "=r"(r[11]),
          "=r"(r[12]), "=r"(r[13]), "=r"(r[14]), "=r"(r[15]),
          "=r"(r[16]), "=r"(r[17]), "=r"(r[18]), "=r"(r[19]),
          "=r"(r[20]), "=r"(r[21]), "=r"(r[22]), "=r"(r[23]),
          "=r"(r[24]), "=r"(r[25]), "=r"(r[26]), "=r"(r[27]),
          "=r"(r[28]), "=r"(r[29]), "=r"(r[30]), "=r"(r[31])
        : "r"(ta));
#else
    for (int i = 0; i < 32; i++) r[i] = 0u;
#endif
}

#define MBAR_INIT(mb, c)  asm volatile("mbarrier.init.shared.b64 [%0], %1;" :: "r"((uint32_t)(mb)), "r"((uint32_t)(c)) : "memory")
#define MBAR_INVAL(mb)    asm volatile("mbarrier.inval.shared.b64 [%0];" :: "r"((uint32_t)(mb)) : "memory")
__device__ __forceinline__ void mbar_wait(uint32_t mb, uint32_t ph) {
#if TC_ENABLED
    asm volatile("{\n\t.reg .pred P1;\n\tWL_%=:\n\t"
        "mbarrier.try_wait.parity.acquire.cta.shared::cta.b64 P1, [%0], %1, 0x989680;\n\t"
        "@P1 bra.uni WD_%=;\n\tbra.uni WL_%=;\n\tWD_%=:\n\t}"
        :: "r"(mb), "r"(ph) : "memory");
#endif
}
#define FENCE_ASYNC()     asm volatile("fence.proxy.async.shared::cta;" ::: "memory")

// cp.async (Ampere+, legal in generic pass)
__device__ __forceinline__ void cp16(uint32_t dst, const void* src) {
    asm volatile("cp.async.cg.shared.global [%0], [%1], 16;" :: "r"(dst), "l"(src));
}
#define CP_COMMIT() asm volatile("cp.async.commit_group;" ::: "memory")
#define CP_WAIT0()  asm volatile("cp.async.wait_group 0;" ::: "memory")

static constexpr uint64_t DESC_BASE_SW128 =
    (uint64_t(2) << 61) | (uint64_t(1) << 46) | (uint64_t(64) << 32) | (uint64_t(1) << 16);
#define MK_DESC(a) (DESC_BASE_SW128 | ((uint64_t)(((uint32_t)(a)) >> 4) & 0x3FFF))
#define QK_IDESC ((1u<<4)|(1u<<7)|(1u<<10)|((128u/8u)<<17)|((128u/16u)<<24))

__device__ __forceinline__ void mma_f16_ss(uint32_t d, uint64_t ad, uint64_t bd, uint32_t idesc, int en) {
#if TC_ENABLED
    asm volatile("{\n\t.reg .pred p;\n\tsetp.ne.u32 p, %4, 0;\n\t"
        "tcgen05.mma.cta_group::1.kind::f16 [%0], %1, %2, %3, {%5, %5, %5, %5}, p;\n\t}"
        :: "r"(d), "l"(ad), "l"(bd), "r"(idesc), "r"((uint32_t)en), "r"(0u) : "memory");
#endif
}

// smem layout (bytes)
#define R_A    0
#define R_B0   65536
#define R_B1   131072
#define R_CTRL 196608
#define MMA_SMEM_BYTES (196608 + 16)
#define STAGE0 0
#define STAGE1 69632

// cp.async load of 4 tiles (hi/lo × khalf), [128 rows][64 bf16], SW128 swizzle
__device__ __forceinline__ void load_tile_pair_ca(uint32_t smb, int region,
        const __nv_bfloat16* __restrict__ hi, const __nv_bfloat16* __restrict__ lo,
        size_t rbase, int rstride) {
    int t = threadIdx.x;
#pragma unroll
    for (int sp = 0; sp < 2; sp++) {
        const __nv_bfloat16* src = sp ? lo : hi;
#pragma unroll
        for (int kh = 0; kh < 2; kh++) {
#pragma unroll
            for (int i = 0; i < 4; i++) {
                int idx = t + i * 256;
                int row = idx >> 3, ch = idx & 7;
                uint32_t off = (uint32_t)(row * 128 + ch * 16);
                off ^= (off >> 3) & 0x70;
                cp16(smb + region + (sp * 2 + kh) * 16384 + off,
                     src + rbase + (size_t)row * rstride + kh * 64 + ch * 8);
            }
        }
    }
}

// 3-chain split MMA: (hi,hi),(hi,lo),(lo,hi), K=128 = 2 khalves × 4 K16 steps
__device__ __forceinline__ void mma_pair(uint32_t d, uint32_t smb, int aoff, int boff, int first) {
    const int asp[3] = {0, 0, 1};
    const int bsp[3] = {0, 1, 0};
#pragma unroll
    for (int s = 0; s < 3; s++) {
#pragma unroll
        for (int kh = 0; kh < 2; kh++) {
            uint64_t ad = MK_DESC(smb + aoff + (asp[s] * 2 + kh) * 16384);
            uint64_t bd = MK_DESC(smb + boff + (bsp[s] * 2 + kh) * 16384);
#pragma unroll
            for (int ks = 0; ks < 4; ks++) {
                int en = !(first && s == 0 && kh == 0 && ks == 0);
                mma_f16_ss(d, ad + ks * 2, bd + ks * 2, QK_IDESC, en);
            }
        }
    }
}

// ---------------- exact k-th order statistic via radix select -----------------
__device__ __forceinline__ float radix_select_smem(const uint32_t* sv, int n, int k,
                                                   uint32_t* hist, int* sh, int nt) {
    int tid = threadIdx.x;
    int n_pad = ((n + nt - 1) / nt) * nt;
    uint32_t prefix = 0;
    int rank = k;
#pragma unroll 1
    for (int shift = 24; shift >= 0; shift -= 8) {
        for (int i = tid; i < 256; i += nt) hist[i] = 0;
        __syncthreads();
        uint32_t pmask = (shift == 24) ? 0u : (0xFFFFFFFFu << (shift + 8));
        for (int i = tid; i < n_pad; i += nt) {
            bool act = false;
            uint32_t bkt = 0x100u;
            if (i < n) {
                uint32_t v = sv[i];
                if ((v & pmask) == prefix) { act = true; bkt = (v >> shift) & 0xFFu; }
            }
            uint32_t grp = __match_any_sync(0xffffffffu, bkt);
            if (act) {
                int leader = __ffs(grp) - 1;
                if ((int)(tid & 31) == leader) atomicAdd(&hist[bkt], __popc(grp));
            }
        }
        __syncthreads();
        if (tid == 0) {
            int acc = 0, bsel = 255;
            for (int bkt = 0; bkt < 256; bkt++) {
                int c = (int)hist[bkt];
                if (acc + c > rank) { bsel = bkt; break; }
                acc += c;
            }
            sh[0] = bsel;
            sh[1] = rank - acc;
        }
        __syncthreads();
        prefix |= ((uint32_t)sh[0]) << shift;
        rank = sh[1];
        __syncthreads();
    }
    return __uint_as_float(prefix);
}

// ---------------- init: twiddles + W split + zero accumulators ----------------
__global__ __launch_bounds__(512) void k_init(const float* __restrict__ WK,
                                              const float* __restrict__ WV) {
    int tid = threadIdx.x;
    for (int idx = tid; idx < 4096; idx += 512) {
        if (idx == 0) { g_tw[0] = make_float2(1.f, 0.f); continue; }
        int s = 31 - __clz(idx);
        int L = 1 << s;
        int k = idx - L;
        float th = 3.14159265358979323846f * (float)k / (float)L;
        g_tw[idx] = make_float2(cosf(th), sinf(th));
    }
    for (int idx = tid; idx < CH * CH; idx += 512) {
        float v = WK[idx];
        __nv_bfloat16 h = __float2bfloat16(v);
        g_wkh[idx] = h;
        g_wkl[idx] = __float2bfloat16(v - __bfloat162float(h));
        v = WV[idx];
        h = __float2bfloat16(v);
        g_wvh[idx] = h;
        g_wvl[idx] = __float2bfloat16(v - __bfloat162float(h));
    }
    for (int idx = tid; idx < BATCH * FT; idx += 512) g_lsum[idx] = 0.f;
    for (int idx = tid; idx < BATCH * NF; idx += 512) g_energy[idx] = 0.f;
}

// ---------------- Stockham radix-2 FFT of 4096 (smem twiddles) ----------------
template <int SIGN>
__device__ __forceinline__ void fft4096(float2* bufA, float2* bufB, const float2* tws) {
    float2* src = bufA;
    float2* dst = bufB;
#pragma unroll 1
    for (int s = 0; s < 12; s++) {
        int L = 1 << s;
        __syncthreads();
        for (int i = threadIdx.x; i < 2048; i += 512) {
            int k = i & (L - 1);
            int j = i >> s;
            float2 u = src[i];
            float2 v = src[i + 2048];
            float2 t = tws[L + k];
            float cw = t.x, sw = (float)SIGN * t.y;
            float2 wv = make_float2(cw * v.x - sw * v.y, cw * v.y + sw * v.x);
            int o = (j << (s + 1)) + k;
            dst[o]     = make_float2(u.x + wv.x, u.y + wv.y);
            dst[o + L] = make_float2(u.x - wv.x, u.y - wv.y);
        }
        float2* t2 = src; src = dst; dst = t2;
    }
    __syncthreads();
}

#define FFT_SMEM (3 * 4096 * sizeof(float2))

__global__ __launch_bounds__(512) void k_fft_fwd(const float* __restrict__ x_in) {
    extern __shared__ float2 sm2[];
    float2* A = sm2;
    float2* Bb = sm2 + 4096;
    float2* tws = sm2 + 8192;
    for (int i = threadIdx.x; i < 4096; i += 512) tws[i] = g_tw[i];
    int bc = blockIdx.x;
    const float* xrow = x_in + (size_t)bc * NT;
    for (int k = threadIdx.x; k < 4096; k += 512) A[k] = make_float2(xrow[k], 0.f);
    fft4096<-1>(A, Bb, tws);
    const float s = 1.0f / SQRTN;
    size_t base = (size_t)bc * FPAD;
    for (int f = threadIdx.x; f < NF; f += 512) {
        g_Xr[base + f] = A[f].x * s;
        g_Xi[base + f] = A[f].y * s;
    }
}

// ------- fp32 X [c][f] -> bf16 hi/lo [f][c] (transpose + split) + energy ------
__global__ __launch_bounds__(256) void k_conv_qk() {
    __shared__ float ts[64][65];
    int ftile = blockIdx.x;            // 0..33
    int b = blockIdx.y >> 1;
    int ch0 = (blockIdx.y & 1) * 64;
    int w = blockIdx.z;                // 0: Xr, 1: Xi
    const float* src = w ? g_Xi : g_Xr;
    __nv_bfloat16* dh = w ? g_qih : g_qrh;
    __nv_bfloat16* dl = w ? g_qil : g_qrl;
    int f0 = ftile * 64;
    size_t sbase = (size_t)b * CH * FPAD;
    int tid = threadIdx.x;
    for (int idx = tid; idx < 4096; idx += 256) {
        int c = idx >> 6, f = idx & 63;
        int gf = f0 + f;
        float v = (gf < NF) ? src[sbase + (size_t)(ch0 + c) * FPAD + gf] : 0.f;
        ts[f][c] = v;
    }
    __syncthreads();
    // energy partial: sum over this 64-channel half of v^2, atomic to g_energy
    {
        int fl = tid >> 2, q = tid & 3;
        float s = 0.f;
#pragma unroll
        for (int j = 0; j < 16; j++) {
            float v = ts[fl][q * 16 + j];
            s = fmaf(v, v, s);
        }
        s += __shfl_down_sync(0xffffffffu, s, 2, 4);
        s += __shfl_down_sync(0xffffffffu, s, 1, 4);
        int gf = f0 + fl;
        if (q == 0 && gf < NF) atomicAdd(&g_energy[b * NF + gf], s);
    }
    for (int idx = tid; idx < 4096; idx += 256) {
        int f = idx >> 6, c = idx & 63;
        float v = ts[f][c];
        __nv_bfloat16 h = __float2bfloat16(v);
        size_t o = ((size_t)b * FT + f0 + f) * CH + ch0 + c;
        dh[o] = h;
        dl[o] = __float2bfloat16(v - __bfloat162float(h));
    }
}

// ---------------- K/V = W x X via tcgen05, bf16 hi/lo outputs -----------------
__global__ __launch_bounds__(256, 1) __cluster_dims__(1, 1, 1)
void k_kv_mma(const float* __restrict__ bK, const float* __restrict__ bV) {
    extern __shared__ char sm[];
    uint32_t smb = smem_u32(sm);
    int tid = threadIdx.x, wid = tid >> 5, lane = tid & 31;
    int f0 = blockIdx.x * 128, b = blockIdx.y, kv = blockIdx.z;

    if (wid == 0) tc_alloc(smb + R_CTRL, 256);
    if (tid == 0) MBAR_INIT(smb + R_CTRL + 8, 1);
    __syncthreads();
    uint32_t tm;
    asm volatile("ld.shared.b32 %0, [%1];" : "=r"(tm) : "r"(smb + R_CTRL));
    uint32_t mbar = smb + R_CTRL + 8;

    const __nv_bfloat16* wh = kv ? g_wvh : g_wkh;
    const __nv_bfloat16* wl = kv ? g_wvl : g_wkl;
    load_tile_pair_ca(smb, R_A, wh, wl, 0, CH);
    size_t xb = ((size_t)b * FT + f0) * CH;
    load_tile_pair_ca(smb, R_B0, g_qrh, g_qrl, xb, CH);
    load_tile_pair_ca(smb, R_B1, g_qih, g_qil, xb, CH);
    CP_COMMIT(); CP_WAIT0();
    FENCE_ASYNC();
    __syncthreads();

    if (wid == 0 && elect_one()) {
        mma_pair(tm, smb, R_A, R_B0, 1);        // D0 = W x Xr
        mma_pair(tm + 128, smb, R_A, R_B1, 1);  // D1 = W x Xi
        tc_commit(mbar);
    }
    mbar_wait(mbar, 0);
    tc_fence_after();

    // stage D0 (warps 0-3) / D1 (warps 4-7) fp32 [m][f], stride 133
    {
        int half = wid >> 2, w4 = wid & 3;
        float* stage = (float*)(sm + (half ? STAGE1 : STAGE0));
        uint32_t dbase = tm + half * 128;
        int row = w4 * 32 + lane;
#pragma unroll
        for (int part = 0; part < 4; part++) {
            uint32_t r[32];
            tc_ld_x32(r, dbase + part * 32);
            tc_wait_ld();
#pragma unroll
            for (int c = 0; c < 32; c++) stage[row * 133 + part * 32 + c] = __uint_as_float(r[c]);
        }
    }
    __syncthreads();
    const float* s0 = (const float*)(sm + STAGE0);
    const float* s1 = (const float*)(sm + STAGE1);
    if (kv == 0) {
        // K: transposed write [f][c]
        for (int idx = tid; idx < 128 * 128; idx += 256) {
            int f = idx >> 7, c = idx & 127;
            float vr = s0[c * 133 + f];
            float vi = s1[c * 133 + f];
            if (f0 == 0 && f == 0) vr += SQRTN * __ldg(&bK[c]);
            size_t o = ((size_t)b * FT + f0 + f) * CH + c;
            __nv_bfloat16 h = __float2bfloat16(vr);
            g_krh[o] = h;
            g_krl[o] = __float2bfloat16(vr - __bfloat162float(h));
            h = __float2bfloat16(vi);
            g_kih[o] = h;
            g_kil[o] = __float2bfloat16(vi - __bfloat162float(h));
        }
    } else {
        // V: direct write [c][g]
        for (int idx = tid; idx < 128 * 128; idx += 256) {
            int c = idx >> 7, f = idx & 127;
            float vr = s0[c * 133 + f];
            float vi = s1[c * 133 + f];
            if (f0 == 0 && f == 0) vr += SQRTN * __ldg(&bV[c]);
            size_t o = ((size_t)b * CH + c) * FT + f0 + f;
            __nv_bfloat16 h = __float2bfloat16(vr);
            g_vrh[o] = h;
            g_vrl[o] = __float2bfloat16(vr - __bfloat162float(h));
            h = __float2bfloat16(vi);
            g_vih[o] = h;
            g_vil[o] = __float2bfloat16(vi - __bfloat162float(h));
        }
    }
    __syncthreads();
    if (tid == 0) MBAR_INVAL(mbar);
    __syncthreads();
    if (wid == 0) tc_dealloc(tm, 256);
}

// ------- QK^T via tcgen05 (4 accums), e = exp(|S|*scale), fused row sums ------
__global__ __launch_bounds__(256, 1) __cluster_dims__(1, 1, 1) void k_qk_mma() {
    extern __shared__ char sm[];
    uint32_t smb = smem_u32(sm);
    int tid = threadIdx.x, wid = tid >> 5, lane = tid & 31;
    int g0 = blockIdx.x * 128, f0 = blockIdx.y * 128, b = blockIdx.z;

    if (wid == 0) tc_alloc(smb + R_CTRL, 512);
    if (tid == 0) MBAR_INIT(smb + R_CTRL + 8, 1);
    __syncthreads();
    uint32_t tm;
    asm volatile("ld.shared.b32 %0, [%1];" : "=r"(tm) : "r"(smb + R_CTRL));
    uint32_t mbar = smb + R_CTRL + 8;

    size_t kb = ((size_t)b * FT + g0) * CH;
    size_t qb = ((size_t)b * FT + f0) * CH;
    load_tile_pair_ca(smb, R_B0, g_krh, g_krl, kb, CH);
    load_tile_pair_ca(smb, R_B1, g_kih, g_kil, kb, CH);
    load_tile_pair_ca(smb, R_A, g_qrh, g_qrl, qb, CH);
    CP_COMMIT(); CP_WAIT0();
    FENCE_ASYNC();
    __syncthreads();

    uint32_t phase = 0;
    if (wid == 0 && elect_one()) {
        mma_pair(tm, smb, R_A, R_B0, 1);        // D0 = Qr*Kr
        mma_pair(tm + 128, smb, R_A, R_B1, 1);  // D1 = Qr*Ki
        tc_commit(mbar);
    }
    mbar_wait(mbar, phase); phase ^= 1;

    load_tile_pair_ca(smb, R_A, g_qih, g_qil, qb, CH);
    CP_COMMIT(); CP_WAIT0();
    FENCE_ASYNC();
    __syncthreads();
    if (wid == 0 && elect_one()) {
        mma_pair(tm + 256, smb, R_A, R_B1, 1);  // D2 = Qi*Ki
        mma_pair(tm + 384, smb, R_A, R_B0, 1);  // D3 = Qi*Kr
        tc_commit(mbar);
    }
    mbar_wait(mbar, phase); phase ^= 1;
    tc_fence_after();

    // warps 0-3: sr = D0 - D2 -> STAGE0; warps 4-7: si = D1 + D3 -> STAGE1
    {
        int half = wid >> 2, w4 = wid & 3;
        float* stage = (float*)(sm + (half ? STAGE1 : STAGE0));
        uint32_t dA = tm + (half ? 128 : 0);
        uint32_t dB = tm + (half ? 384 : 256);
        int row = w4 * 32 + lane;
#pragma unroll
        for (int part = 0; part < 4; part++) {
            uint32_t ra[32], rb[32];
            tc_ld_x32(ra, dA + part * 32);
            tc_ld_x32(rb, dB + part * 32);
            tc_wait_ld();
#pragma unroll
            for (int c = 0; c < 32; c++) {
                float fa = __uint_as_float(ra[c]);
                float fb = __uint_as_float(rb[c]);
                stage[row * 132 + part * 32 + c] = half ? (fa + fb) : (fa - fb);
            }
        }
    }
    __syncthreads();
    {
        const float* str = (const float*)(sm + STAGE0);
        const float* sti = (const float*)(sm + STAGE1);
        size_t sbase = ((size_t)b * FT + f0) * FT + g0;
        for (int idx = tid; idx < 128 * 128; idx += 256) {
            int row = idx >> 7, col = idx & 127;
            float sr = str[row * 132 + col], si = sti[row * 132 + col];
            float u = fmaxf(fmaf(sr, sr, si * si), 1e-30f);
            float y = __int_as_float(0x5f3759df - (__float_as_int(u) >> 1));
            float hu = 0.5f * u;
            y = y * (1.5f - hu * y * y);
            y = y * (1.5f - hu * y * y);
            float m = u * y;
            float e = (g0 + col < NF) ? __expf(m * ATT_SCALE) : 0.f;
            g_S[sbase + (size_t)row * FT + col] = e;
            // fused row-sum (all lanes in warp share `row`)
            float s = e;
#pragma unroll
            for (int mm = 16; mm; mm >>= 1) s += __shfl_xor_sync(0xffffffffu, s, mm);
            if (lane == 0) atomicAdd(&g_lsum[(size_t)b * FT + f0 + row], s);
        }
    }
    __syncthreads();
    if (tid == 0) MBAR_INVAL(mbar);
    __syncthreads();
    if (wid == 0) tc_dealloc(tm, 512);
}

// ---------------- O = P @ V via tcgen05; P built on-the-fly -------------------
__global__ __launch_bounds__(256, 1) __cluster_dims__(1, 1, 1) void k_av_mma() {
    extern __shared__ char sm[];
    __shared__ float invl_s[128];
    uint32_t smb = smem_u32(sm);
    int tid = threadIdx.x, wid = tid >> 5, lane = tid & 31;
    int f0 = blockIdx.x * 128, b = blockIdx.y;
    if (wid == 0) tc_alloc(smb + R_CTRL, 256);
    if (tid == 0) MBAR_INIT(smb + R_CTRL + 8, 1);
    if (tid < 128) {
        float ls = g_lsum[(size_t)b * FT + f0 + tid];
        invl_s[tid] = (ls > 0.f) ? 1.0f / ls : 0.f;
    }
    __syncthreads();
    uint32_t tm;
    asm volatile("ld.shared.b32 %0, [%1];" : "=r"(tm) : "r"(smb + R_CTRL));
    uint32_t mbar = smb + R_CTRL + 8;
    uint32_t phase = 0;
    for (int kt = 0; kt < 17; kt++) {
        int g0 = kt * 128;
        // async V loads first (overlap with P build below)
        size_t vb = ((size_t)b * CH) * FT + g0;
        load_tile_pair_ca(smb, R_B0, g_vrh, g_vrl, vb, FT);
        load_tile_pair_ca(smb, R_B1, g_vih, g_vil, vb, FT);
        CP_COMMIT();
        // build A = P tile (bf16 hi/lo, swizzled) from e * invl
#pragma unroll
        for (int i = 0; i < 8; i++) {
            int chunk = tid + i * 256;
            int row = chunk >> 4, c8 = (chunk & 15) * 8;
            const float* srow = g_S + ((size_t)b * FT + f0 + row) * FT + g0 + c8;
            float4 ea = *(const float4*)srow;
            float4 eb = *(const float4*)(srow + 4);
            float iv = invl_s[row];
            float pv[8] = {ea.x * iv, ea.y * iv, ea.z * iv, ea.w * iv,
                           eb.x * iv, eb.y * iv, eb.z * iv, eb.w * iv};
            uint32_t hiw[4], low[4];
#pragma unroll
            for (int j = 0; j < 4; j++) {
                __nv_bfloat162 h2 = __floats2bfloat162_rn(pv[2 * j], pv[2 * j + 1]);
                hiw[j] = *(uint32_t*)&h2;
                float l0 = pv[2 * j]     - __bfloat162float(__low2bfloat16(h2));
                float l1 = pv[2 * j + 1] - __bfloat162float(__high2bfloat16(h2));
                __nv_bfloat162 l2 = __floats2bfloat162_rn(l0, l1);
                low[j] = *(uint32_t*)&l2;
            }
            int kh = c8 >> 6;
            uint32_t off = (uint32_t)(row * 128 + (c8 & 63) * 2);
            off ^= (off >> 3) & 0x70;
            *(uint4*)(sm + R_A + kh * 16384 + off)       = make_uint4(hiw[0], hiw[1], hiw[2], hiw[3]);
            *(uint4*)(sm + R_A + (2 + kh) * 16384 + off) = make_uint4(low[0], low[1], low[2], low[3]);
        }
        CP_WAIT0();
        FENCE_ASYNC();
        __syncthreads();
        if (wid == 0 && elect_one()) {
            mma_pair(tm, smb, R_A, R_B0, kt == 0);        // Or += P*Vr
            mma_pair(tm + 128, smb, R_A, R_B1, kt == 0);  // Oi += P*Vi
            tc_commit(mbar);
        }
        mbar_wait(mbar, phase); phase ^= 1;
    }
    tc_fence_after();
    {
        int half = wid >> 2, w4 = wid & 3;
        float* stage = (float*)(sm + (half ? STAGE1 : STAGE0));
        uint32_t dbase = tm + half * 128;
        int row = w4 * 32 + lane;
#pragma unroll
        for (int part = 0; part < 4; part++) {
            uint32_t r[32];
            tc_ld_x32(r, dbase + part * 32);
            tc_wait_ld();
#pragma unroll
            for (int c = 0; c < 32; c++) stage[row * 132 + part * 32 + c] = __uint_as_float(r[c]);
        }
    }
    __syncthreads();
    {
        const float* str = (const float*)(sm + STAGE0);
        const float* sti = (const float*)(sm + STAGE1);
        for (int idx = tid; idx < 128 * 128; idx += 256) {
            int c = idx >> 7, fl = idx & 127;
            int gf = f0 + fl;
            if (gf < NF) {
                size_t o = ((size_t)b * CH + c) * FPAD + gf;
                g_Or[o] = str[fl * 132 + c];
                g_Oi[o] = sti[fl * 132 + c];
            }
        }
    }
    __syncthreads();
    if (tid == 0) MBAR_INVAL(mbar);
    __syncthreads();
    if (wid == 0) tc_dealloc(tm, 256);
}

// ---------------- median (exact radix select per batch) -----------------------
__global__ __launch_bounds__(256) void k_median() {
    __shared__ uint32_t sv[NF];
    __shared__ uint32_t hist[256];
    __shared__ int sh[2];
    int b = blockIdx.x;
    for (int i = threadIdx.x; i < NF; i += 256) sv[i] = __float_as_uint(g_energy[b * NF + i]);
    __syncthreads();
    float m = radix_select_smem(sv, NF, NF / 2, hist, sh, 256);
    if (threadIdx.x == 0) g_med[b] = m;
}

// ------- global quantile (fused normalize; exact radix select) ----------------
#define QSEL_N (BATCH * NF)
#define QSEL_SMEM ((QSEL_N + 256 + 2) * 4)
__global__ __launch_bounds__(512) void k_quantile(const float* __restrict__ qparam) {
    extern __shared__ uint32_t qsm[];
    uint32_t* sv = qsm;
    uint32_t* hist = qsm + QSEL_N;
    int* sh = (int*)(hist + 256);
    for (int i = threadIdx.x; i < QSEL_N; i += 512) {
        int b = i / NF;
        float v = g_energy[i] / (g_med[b] + 1e-6f);
        g_normv[i] = v;
        sv[i] = __float_as_uint(v);
    }
    __syncthreads();
    float q = qparam[0];
    float pos = q * (float)(QSEL_N - 1);
    int lo = (int)floorf(pos);
    if (lo < 0) lo = 0;
    if (lo > QSEL_N - 2) lo = QSEL_N - 2;
    float frac = pos - (float)lo;
    float a = radix_select_smem(sv, QSEL_N, lo, hist, sh, 512);
    __syncthreads();
    float bb = radix_select_smem(sv, QSEL_N, lo + 1, hist, sh, 512);
    if (threadIdx.x == 0) g_thr[0] = a + (bb - a) * frac;
}

// ---------------- inverse rfft (fused hi-freq mask) -> output (B,C,N) ---------
__global__ __launch_bounds__(512) void k_ifft(float* __restrict__ out,
                                              const float* __restrict__ w_high) {
    extern __shared__ float2 sm2[];
    float2* A = sm2;
    float2* Bb = sm2 + 4096;
    float2* tws = sm2 + 8192;
    for (int i = threadIdx.x; i < 4096; i += 512) tws[i] = g_tw[i];
    int bc = blockIdx.x;
    int b = bc >> 7, c = bc & 127;
    float whr = w_high[c * 2], whi = w_high[c * 2 + 1];
    float thr = g_thr[0];
    size_t base = (size_t)bc * FPAD;
    for (int k = threadIdx.x; k < 4096; k += 512) {
        int kk = (k <= 2048) ? k : (4096 - k);
        float sgn = (k <= 2048) ? 1.f : -1.f;
        float oR = g_Or[base + kk];
        float oI = g_Oi[base + kk];
        if (g_normv[b * NF + kk] > thr) {
            float xr = g_Xr[base + kk], xi = g_Xi[base + kk];
            oR += xr * whr - xi * whi;
            oI += xr * whi + xi * whr;
        }
        A[k] = make_float2(oR, sgn * oI);
    }
    fft4096<1>(A, Bb, tws);
    const float s = 1.0f / SQRTN;
    float* orow = out + (size_t)bc * NT;
    for (int n = threadIdx.x; n < 4096; n += 512) orow[n] = A[n].x * s;
}

// ---------------- launch -------------------------------------------------------
extern "C" void kernel_launch(void* const* d_in, const int* in_sizes, int n_in,
                              void* d_out, int out_size) {
    const float* x_in   = (const float*)d_in[0];
    const float* W_K    = (const float*)d_in[1];
    const float* b_K    = (const float*)d_in[2];
    const float* W_V    = (const float*)d_in[3];
    const float* b_V    = (const float*)d_in[4];
    const float* w_high = (const float*)d_in[5];
    const float* qparam = (const float*)d_in[6];
    float* out = (float*)d_out;

    cudaFuncSetAttribute(k_fft_fwd,  cudaFuncAttributeMaxDynamicSharedMemorySize, FFT_SMEM);
    cudaFuncSetAttribute(k_ifft,     cudaFuncAttributeMaxDynamicSharedMemorySize, FFT_SMEM);
    cudaFuncSetAttribute(k_kv_mma,   cudaFuncAttributeMaxDynamicSharedMemorySize, MMA_SMEM_BYTES);
    cudaFuncSetAttribute(k_qk_mma,   cudaFuncAttributeMaxDynamicSharedMemorySize, MMA_SMEM_BYTES);
    cudaFuncSetAttribute(k_av_mma,   cudaFuncAttributeMaxDynamicSharedMemorySize, MMA_SMEM_BYTES);
    cudaFuncSetAttribute(k_quantile, cudaFuncAttributeMaxDynamicSharedMemorySize, QSEL_SMEM);

    k_init<<<1, 512>>>(W_K, W_V);
    k_fft_fwd<<<BATCH * CH, 512, FFT_SMEM>>>(x_in);
    k_conv_qk<<<dim3(34, 16, 2), 256>>>();
    k_kv_mma<<<dim3(17, 8, 2), 256, MMA_SMEM_BYTES>>>(b_K, b_V);
    k_qk_mma<<<dim3(17, 17, 8), 256, MMA_SMEM_BYTES>>>();
    k_av_mma<<<dim3(17, 8), 256, MMA_SMEM_BYTES>>>();
    k_median<<<BATCH, 256>>>();
    k_quantile<<<1, 512, QSEL_SMEM>>>(qparam);
    k_ifft<<<BATCH * CH, 512, FFT_SMEM>>>(out, w_high);
}

// round 12
// speedup vs baseline: 2.0023x; 2.0023x over previous
#include <cuda_runtime.h>
#include <cuda_bf16.h>
#include <math.h>
#include <stdint.h>

#define BATCH 8
#define CH    128
#define NT    4096
#define NF    2049
#define FPAD  2064
#define FT    2176          /* padded F for tensor path: 17*128 */
#define SQRTN 64.0f
#define ATT_SCALE 0.08838834764831845f  /* 1/sqrt(128) */

#if defined(__CUDA_ARCH_FEAT_SM103_ALL) || defined(__CUDA_ARCH_FEAT_SM100_ALL)
#define TC_ENABLED 1
#else
#define TC_ENABLED 0
#endif

// ---------------- scratch ------------------------------------------------------
__device__ float g_Xr[BATCH*CH*FPAD];
__device__ float g_Xi[BATCH*CH*FPAD];
__device__ float g_Or[BATCH*CH*FPAD];
__device__ float g_Oi[BATCH*CH*FPAD];
__device__ float g_energy[BATCH*NF];
__device__ float g_normv[BATCH*NF];
__device__ float g_med[BATCH];
__device__ float g_thr[1];
__device__ float2 g_tw[4096];
__device__ float g_lsum[BATCH*FT];     /* row sums of e (atomic) */

#define QKN ((size_t)BATCH*FT*CH)     /* [b][f][c] */
#define VN  ((size_t)BATCH*CH*FT)     /* [b][c][g] */
#define PN  ((size_t)BATCH*FT*FT)     /* [b][f][g] */
__device__ __align__(256) __nv_bfloat16 g_qrh[QKN], g_qrl[QKN];
__device__ __align__(256) __nv_bfloat16 g_qih[QKN], g_qil[QKN];
__device__ __align__(256) __nv_bfloat16 g_krh[QKN], g_krl[QKN];
__device__ __align__(256) __nv_bfloat16 g_kih[QKN], g_kil[QKN];
__device__ __align__(256) __nv_bfloat16 g_vrh[VN],  g_vrl[VN];
__device__ __align__(256) __nv_bfloat16 g_vih[VN],  g_vil[VN];
__device__ __align__(256) __nv_bfloat16 g_wkh[CH*CH], g_wkl[CH*CH];
__device__ __align__(256) __nv_bfloat16 g_wvh[CH*CH], g_wvl[CH*CH];
__device__ __align__(256) float g_S[PN];   /* e = exp(|S|*scale) */

// ================= tcgen05 helpers (feature-gated) ============================
__device__ __forceinline__ uint32_t smem_u32(const void* p) {
    uint32_t a;
    asm("{ .reg .u64 t; cvta.to.shared.u64 t, %1; cvt.u32.u64 %0, t; }" : "=r"(a) : "l"(p));
    return a;
}
__device__ __forceinline__ uint32_t elect_one() {
    uint32_t p;
    asm volatile("{ .reg .pred p; elect.sync _|p, 0xFFFFFFFF; selp.b32 %0, 1, 0, p; }" : "=r"(p));
    return p;
}
__device__ __forceinline__ void tc_alloc(uint32_t sa, uint32_t n) {
#if TC_ENABLED
    asm volatile("tcgen05.alloc.cta_group::1.sync.aligned.shared::cta.b32 [%0], %1;" :: "r"(sa), "r"(n) : "memory");
#endif
}
__device__ __forceinline__ void tc_dealloc(uint32_t tm, uint32_t n) {
#if TC_ENABLED
    asm volatile("tcgen05.dealloc.cta_group::1.sync.aligned.b32 %0, %1;" :: "r"(tm), "r"(n));
#endif
}
__device__ __forceinline__ void tc_commit(uint32_t mb) {
#if TC_ENABLED
    asm volatile("tcgen05.commit.cta_group::1.mbarrier::arrive::one.shared::cluster.b64 [%0];" :: "r"(mb) : "memory");
#endif
}
__device__ __forceinline__ void tc_wait_ld() {
#if TC_ENABLED
    asm volatile("tcgen05.wait::ld.sync.aligned;" ::: "memory");
#endif
}
__device__ __forceinline__ void tc_fence_after() {
#if TC_ENABLED
    asm volatile("tcgen05.fence::after_thread_sync;" ::: "memory");
#endif
}
__device__ __forceinline__ void tc_fence_before() {
#if TC_ENABLED
    asm volatile("tcgen05.fence::before_thread_sync;" ::: "memory");
#endif
}
__device__ __forceinline__ void tc_ld_x32(uint32_t* r, uint32_t ta) {
#if TC_ENABLED
    asm volatile("tcgen05.ld.sync.aligned.32x32b.x32.b32 "
        "{%0, %1, %2, %3, %4, %5, %6, %7, %8, %9, %10, %11, %12, %13, %14, %15, "
        " %16, %17, %18, %19, %20, %21, %22, %23, %24, %25, %26, %27, %28, %29, %30, %31}, [%32];"
        : "=r"(r[0]),  "=r"(r[1]),  "=r"(r[2]),  "=r"(r[3]),
          "=r"(r[4]),  "=r"(r[5]),  "=r"(r[6]),  "=r"(r[7]),
          "=r"(r[8]),  "=r"(r[9]),  "=r"(r[10]), "=r"(r[11]),
          "=r"(r[12]), "=r"(r[13]), "=r"(r[14]), "=r"(r[15]),
          "=r"(r[16]), "=r"(r[17]), "=r"(r[18]), "=r"(r[19]),
          "=r"(r[20]), "=r"(r[21]), "=r"(r[22]), "=r"(r[23]),
          "=r"(r[24]), "=r"(r[25]), "=r"(r[26]), "=r"(r[27]),
          "=r"(r[28]), "=r"(r[29]), "=r"(r[30]), "=r"(r[31])
        : "r"(ta));
#else
    for (int i = 0; i < 32; i++) r[i] = 0u;
#endif
}

#define MBAR_INIT(mb, c)  asm volatile("mbarrier.init.shared.b64 [%0], %1;" :: "r"((uint32_t)(mb)), "r"((uint32_t)(c)) : "memory")
#define MBAR_INVAL(mb)    asm volatile("mbarrier.inval.shared.b64 [%0];" :: "r"((uint32_t)(mb)) : "memory")
__device__ __forceinline__ void mbar_wait(uint32_t mb, uint32_t ph) {
#if TC_ENABLED
    asm volatile("{\n\t.reg .pred P1;\n\tWL_%=:\n\t"
        "mbarrier.try_wait.parity.acquire.cta.shared::cta.b64 P1, [%0], %1, 0x989680;\n\t"
        "@P1 bra.uni WD_%=;\n\tbra.uni WL_%=;\n\tWD_%=:\n\t}"
        :: "r"(mb), "r"(ph) : "memory");
#endif
}
#define FENCE_ASYNC()     asm volatile("fence.proxy.async.shared::cta;" ::: "memory")

__device__ __forceinline__ void cp16(uint32_t dst, const void* src) {
    asm volatile("cp.async.cg.shared.global [%0], [%1], 16;" :: "r"(dst), "l"(src));
}
#define CP_COMMIT() asm volatile("cp.async.commit_group;" ::: "memory")
#define CP_WAIT0()  asm volatile("cp.async.wait_group 0;" ::: "memory")

static constexpr uint64_t DESC_BASE_SW128 =
    (uint64_t(2) << 61) | (uint64_t(1) << 46) | (uint64_t(64) << 32) | (uint64_t(1) << 16);
#define MK_DESC(a) (DESC_BASE_SW128 | ((uint64_t)(((uint32_t)(a)) >> 4) & 0x3FFF))
#define QK_IDESC ((1u<<4)|(1u<<7)|(1u<<10)|((128u/8u)<<17)|((128u/16u)<<24))

__device__ __forceinline__ void mma_f16_ss(uint32_t d, uint64_t ad, uint64_t bd, uint32_t idesc, int en) {
#if TC_ENABLED
    asm volatile("{\n\t.reg .pred p;\n\tsetp.ne.u32 p, %4, 0;\n\t"
        "tcgen05.mma.cta_group::1.kind::f16 [%0], %1, %2, %3, {%5, %5, %5, %5}, p;\n\t}"
        :: "r"(d), "l"(ad), "l"(bd), "r"(idesc), "r"((uint32_t)en), "r"(0u) : "memory");
#endif
}

// smem layout kv/av (bytes)
#define R_A    0
#define R_B0   65536
#define R_B1   131072
#define R_CTRL 196608
#define MMA_SMEM_BYTES (196608 + 16)
#define STAGE0 0
#define STAGE1 69632

// smem layout strip-mined QK
#define R_QR   0
#define R_QI   65536
#define R_KB   131072
#define R_QCTL 196608
#define R_STG  196624
#define QK_SMEM_BYTES (196624 + 2 * 16896)   /* 230416 */

// cp.async load of 4 tiles (hi/lo × khalf), [128 rows][64 bf16], SW128 swizzle
__device__ __forceinline__ void load_tile_pair_ca(uint32_t smb, int region,
        const __nv_bfloat16* __restrict__ hi, const __nv_bfloat16* __restrict__ lo,
        size_t rbase, int rstride) {
    int t = threadIdx.x;
#pragma unroll
    for (int sp = 0; sp < 2; sp++) {
        const __nv_bfloat16* src = sp ? lo : hi;
#pragma unroll
        for (int kh = 0; kh < 2; kh++) {
#pragma unroll
            for (int i = 0; i < 4; i++) {
                int idx = t + i * 256;
                int row = idx >> 3, ch = idx & 7;
                uint32_t off = (uint32_t)(row * 128 + ch * 16);
                off ^= (off >> 3) & 0x70;
                cp16(smb + region + (sp * 2 + kh) * 16384 + off,
                     src + rbase + (size_t)row * rstride + kh * 64 + ch * 8);
            }
        }
    }
}

// one [128 rows][64 bf16] khalf tile (stride CH)
__device__ __forceinline__ void load_khalf_tile(uint32_t smb, int dstoff,
        const __nv_bfloat16* __restrict__ src, size_t rbase, int kh) {
    int t = threadIdx.x;
#pragma unroll
    for (int i = 0; i < 4; i++) {
        int idx = t + i * 256;
        int row = idx >> 3, ch = idx & 7;
        uint32_t off = (uint32_t)(row * 128 + ch * 16);
        off ^= (off >> 3) & 0x70;
        cp16(smb + dstoff + off, src + rbase + (size_t)row * CH + kh * 64 + ch * 8);
    }
}

__device__ __forceinline__ void load_qk_bchunk(uint32_t smb, size_t kb, int kh) {
    load_khalf_tile(smb, R_KB + 0,     g_krh, kb, kh);
    load_khalf_tile(smb, R_KB + 16384, g_krl, kb, kh);
    load_khalf_tile(smb, R_KB + 32768, g_kih, kb, kh);
    load_khalf_tile(smb, R_KB + 49152, g_kil, kb, kh);
    CP_COMMIT();
}

// 3-chain split MMA (kv/av): (hi,hi),(hi,lo),(lo,hi), 2 khalves × 4 K16 steps
__device__ __forceinline__ void mma_pair(uint32_t d, uint32_t smb, int aoff, int boff, int first) {
    const int asp[3] = {0, 0, 1};
    const int bsp[3] = {0, 1, 0};
#pragma unroll
    for (int s = 0; s < 3; s++) {
#pragma unroll
        for (int kh = 0; kh < 2; kh++) {
            uint64_t ad = MK_DESC(smb + aoff + (asp[s] * 2 + kh) * 16384);
            uint64_t bd = MK_DESC(smb + boff + (bsp[s] * 2 + kh) * 16384);
#pragma unroll
            for (int ks = 0; ks < 4; ks++) {
                int en = !(first && s == 0 && kh == 0 && ks == 0);
                mma_f16_ss(d, ad + ks * 2, bd + ks * 2, QK_IDESC, en);
            }
        }
    }
}

// QK strip: 48 MMAs for one khalf chunk, 4 accumulators
__device__ __forceinline__ void qk_mma_khalf(uint32_t tm, uint32_t smb, int kh) {
    // acc 0: Qr*Kr, 1: Qr*Ki, 2: Qi*Ki, 3: Qi*Kr
#pragma unroll
    for (int acc = 0; acc < 4; acc++) {
        uint32_t Ap = (acc < 2) ? R_QR : R_QI;
        uint32_t Bh = R_KB + ((acc == 0 || acc == 3) ? 0 : 32768);
        uint32_t Ah = Ap + kh * 16384;
        uint32_t Al = Ap + 32768 + kh * 16384;
        uint32_t d = tm + acc * 128;
#pragma unroll
        for (int s = 0; s < 3; s++) {
            uint64_t ad = MK_DESC(smb + ((s == 2) ? Al : Ah));
            uint64_t bd = MK_DESC(smb + ((s == 1) ? (Bh + 16384) : Bh));
#pragma unroll
            for (int ks = 0; ks < 4; ks++) {
                int en = !(kh == 0 && s == 0 && ks == 0);
                mma_f16_ss(d, ad + ks * 2, bd + ks * 2, QK_IDESC, en);
            }
        }
    }
}

// ---------------- exact k-th order statistic via radix select -----------------
__device__ __forceinline__ float radix_select_smem(const uint32_t* sv, int n, int k,
                                                   uint32_t* hist, int* sh, int nt) {
    int tid = threadIdx.x;
    int n_pad = ((n + nt - 1) / nt) * nt;
    uint32_t prefix = 0;
    int rank = k;
#pragma unroll 1
    for (int shift = 24; shift >= 0; shift -= 8) {
        for (int i = tid; i < 256; i += nt) hist[i] = 0;
        __syncthreads();
        uint32_t pmask = (shift == 24) ? 0u : (0xFFFFFFFFu << (shift + 8));
        for (int i = tid; i < n_pad; i += nt) {
            bool act = false;
            uint32_t bkt = 0x100u;
            if (i < n) {
                uint32_t v = sv[i];
                if ((v & pmask) == prefix) { act = true; bkt = (v >> shift) & 0xFFu; }
            }
            uint32_t grp = __match_any_sync(0xffffffffu, bkt);
            if (act) {
                int leader = __ffs(grp) - 1;
                if ((int)(tid & 31) == leader) atomicAdd(&hist[bkt], __popc(grp));
            }
        }
        __syncthreads();
        if (tid == 0) {
            int acc = 0, bsel = 255;
            for (int bkt = 0; bkt < 256; bkt++) {
                int c = (int)hist[bkt];
                if (acc + c > rank) { bsel = bkt; break; }
                acc += c;
            }
            sh[0] = bsel;
            sh[1] = rank - acc;
        }
        __syncthreads();
        prefix |= ((uint32_t)sh[0]) << shift;
        rank = sh[1];
        __syncthreads();
    }
    return __uint_as_float(prefix);
}

// ---------------- init ---------------------------------------------------------
__global__ __launch_bounds__(512) void k_init(const float* __restrict__ WK,
                                              const float* __restrict__ WV) {
    int tid = threadIdx.x;
    for (int idx = tid; idx < 4096; idx += 512) {
        if (idx == 0) { g_tw[0] = make_float2(1.f, 0.f); continue; }
        int s = 31 - __clz(idx);
        int L = 1 << s;
        int k = idx - L;
        float th = 3.14159265358979323846f * (float)k / (float)L;
        g_tw[idx] = make_float2(cosf(th), sinf(th));
    }
    for (int idx = tid; idx < CH * CH; idx += 512) {
        float v = WK[idx];
        __nv_bfloat16 h = __float2bfloat16(v);
        g_wkh[idx] = h;
        g_wkl[idx] = __float2bfloat16(v - __bfloat162float(h));
        v = WV[idx];
        h = __float2bfloat16(v);
        g_wvh[idx] = h;
        g_wvl[idx] = __float2bfloat16(v - __bfloat162float(h));
    }
    for (int idx = tid; idx < BATCH * FT; idx += 512) g_lsum[idx] = 0.f;
    for (int idx = tid; idx < BATCH * NF; idx += 512) g_energy[idx] = 0.f;
}

// ---------------- radix-4 Stockham FFT of 4096 (smem twiddles) ----------------
// Derived by fusing radix-2 stages s, s+1 (L = 4^s): w1 = tw[L+k], W = tw[2L+k];
// w2(k+tL) = W * (SIGN*i)^t handled via the iWB1 rotation.
template <int SIGN>
__device__ __forceinline__ void fft4096_r4(float2* bufA, float2* bufB, const float2* tws) {
    float2* src = bufA;
    float2* dst = bufB;
#pragma unroll 1
    for (int s = 0; s < 6; s++) {
        int sh = 2 * s;
        int L = 1 << sh;
        __syncthreads();
        for (int i = threadIdx.x; i < 1024; i += 512) {
            int k = i & (L - 1);
            int j = i >> sh;
            float2 x0 = src[i];
            float2 x1 = src[i + 1024];
            float2 x2 = src[i + 2048];
            float2 x3 = src[i + 3072];
            float2 w = tws[L + k];
            float2 W = tws[2 * L + k];
            float ws = (float)SIGN * w.y, Ws = (float)SIGN * W.y;
            float2 wx2 = make_float2(w.x * x2.x - ws * x2.y, w.x * x2.y + ws * x2.x);
            float2 wx3 = make_float2(w.x * x3.x - ws * x3.y, w.x * x3.y + ws * x3.x);
            float2 A0 = make_float2(x0.x + wx2.x, x0.y + wx2.y);
            float2 A1 = make_float2(x0.x - wx2.x, x0.y - wx2.y);
            float2 B0 = make_float2(x1.x + wx3.x, x1.y + wx3.y);
            float2 B1 = make_float2(x1.x - wx3.x, x1.y - wx3.y);
            float2 WB0 = make_float2(W.x * B0.x - Ws * B0.y, W.x * B0.y + Ws * B0.x);
            float2 WB1 = make_float2(W.x * B1.x - Ws * B1.y, W.x * B1.y + Ws * B1.x);
            float2 iWB1 = make_float2(-(float)SIGN * WB1.y, (float)SIGN * WB1.x);
            int o = (j << (sh + 2)) + k;
            dst[o]         = make_float2(A0.x + WB0.x, A0.y + WB0.y);
            dst[o + L]     = make_float2(A1.x + iWB1.x, A1.y + iWB1.y);
            dst[o + 2 * L] = make_float2(A0.x - WB0.x, A0.y - WB0.y);
            dst[o + 3 * L] = make_float2(A1.x - iWB1.x, A1.y - iWB1.y);
        }
        float2* t2 = src; src = dst; dst = t2;
    }
    __syncthreads();
}

#define FFT_SMEM (3 * 4096 * sizeof(float2))

__global__ __launch_bounds__(512) void k_fft_fwd(const float* __restrict__ x_in) {
    extern __shared__ float2 sm2[];
    float2* A = sm2;
    float2* Bb = sm2 + 4096;
    float2* tws = sm2 + 8192;
    for (int i = threadIdx.x; i < 4096; i += 512) tws[i] = g_tw[i];
    int bc = blockIdx.x;
    const float* xrow = x_in + (size_t)bc * NT;
    for (int k = threadIdx.x; k < 4096; k += 512) A[k] = make_float2(xrow[k], 0.f);
    fft4096_r4<-1>(A, Bb, tws);
    const float s = 1.0f / SQRTN;
    size_t base = (size_t)bc * FPAD;
    for (int f = threadIdx.x; f < NF; f += 512) {
        g_Xr[base + f] = A[f].x * s;
        g_Xi[base + f] = A[f].y * s;
    }
}

// ------- fp32 X [c][f] -> bf16 hi/lo [f][c] (transpose + split) + energy ------
__global__ __launch_bounds__(256) void k_conv_qk() {
    __shared__ float ts[64][65];
    int ftile = blockIdx.x;
    int b = blockIdx.y >> 1;
    int ch0 = (blockIdx.y & 1) * 64;
    int w = blockIdx.z;
    const float* src = w ? g_Xi : g_Xr;
    __nv_bfloat16* dh = w ? g_qih : g_qrh;
    __nv_bfloat16* dl = w ? g_qil : g_qrl;
    int f0 = ftile * 64;
    size_t sbase = (size_t)b * CH * FPAD;
    int tid = threadIdx.x;
    for (int idx = tid; idx < 4096; idx += 256) {
        int c = idx >> 6, f = idx & 63;
        int gf = f0 + f;
        float v = (gf < NF) ? src[sbase + (size_t)(ch0 + c) * FPAD + gf] : 0.f;
        ts[f][c] = v;
    }
    __syncthreads();
    {
        int fl = tid >> 2, q = tid & 3;
        float s = 0.f;
#pragma unroll
        for (int j = 0; j < 16; j++) {
            float v = ts[fl][q * 16 + j];
            s = fmaf(v, v, s);
        }
        s += __shfl_down_sync(0xffffffffu, s, 2, 4);
        s += __shfl_down_sync(0xffffffffu, s, 1, 4);
        int gf = f0 + fl;
        if (q == 0 && gf < NF) atomicAdd(&g_energy[b * NF + gf], s);
    }
    for (int idx = tid; idx < 4096; idx += 256) {
        int f = idx >> 6, c = idx & 63;
        float v = ts[f][c];
        __nv_bfloat16 h = __float2bfloat16(v);
        size_t o = ((size_t)b * FT + f0 + f) * CH + ch0 + c;
        dh[o] = h;
        dl[o] = __float2bfloat16(v - __bfloat162float(h));
    }
}

// ---------------- K/V = W x X via tcgen05, bf16 hi/lo outputs -----------------
__global__ __launch_bounds__(256, 1) __cluster_dims__(1, 1, 1)
void k_kv_mma(const float* __restrict__ bK, const float* __restrict__ bV) {
    extern __shared__ char sm[];
    uint32_t smb = smem_u32(sm);
    int tid = threadIdx.x, wid = tid >> 5, lane = tid & 31;
    int f0 = blockIdx.x * 128, b = blockIdx.y, kv = blockIdx.z;

    if (wid == 0) tc_alloc(smb + R_CTRL, 256);
    if (tid == 0) MBAR_INIT(smb + R_CTRL + 8, 1);
    __syncthreads();
    uint32_t tm;
    asm volatile("ld.shared.b32 %0, [%1];" : "=r"(tm) : "r"(smb + R_CTRL));
    uint32_t mbar = smb + R_CTRL + 8;

    const __nv_bfloat16* wh = kv ? g_wvh : g_wkh;
    const __nv_bfloat16* wl = kv ? g_wvl : g_wkl;
    load_tile_pair_ca(smb, R_A, wh, wl, 0, CH);
    size_t xb = ((size_t)b * FT + f0) * CH;
    load_tile_pair_ca(smb, R_B0, g_qrh, g_qrl, xb, CH);
    load_tile_pair_ca(smb, R_B1, g_qih, g_qil, xb, CH);
    CP_COMMIT(); CP_WAIT0();
    FENCE_ASYNC();
    __syncthreads();

    if (wid == 0 && elect_one()) {
        mma_pair(tm, smb, R_A, R_B0, 1);
        mma_pair(tm + 128, smb, R_A, R_B1, 1);
        tc_commit(mbar);
    }
    mbar_wait(mbar, 0);
    tc_fence_after();

    {
        int half = wid >> 2, w4 = wid & 3;
        float* stage = (float*)(sm + (half ? STAGE1 : STAGE0));
        uint32_t dbase = tm + half * 128;
        int row = w4 * 32 + lane;
#pragma unroll
        for (int part = 0; part < 4; part++) {
            uint32_t r[32];
            tc_ld_x32(r, dbase + part * 32);
            tc_wait_ld();
#pragma unroll
            for (int c = 0; c < 32; c++) stage[row * 133 + part * 32 + c] = __uint_as_float(r[c]);
        }
    }
    __syncthreads();
    const float* s0 = (const float*)(sm + STAGE0);
    const float* s1 = (const float*)(sm + STAGE1);
    if (kv == 0) {
        for (int idx = tid; idx < 128 * 128; idx += 256) {
            int f = idx >> 7, c = idx & 127;
            float vr = s0[c * 133 + f];
            float vi = s1[c * 133 + f];
            if (f0 == 0 && f == 0) vr += SQRTN * __ldg(&bK[c]);
            size_t o = ((size_t)b * FT + f0 + f) * CH + c;
            __nv_bfloat16 h = __float2bfloat16(vr);
            g_krh[o] = h;
            g_krl[o] = __float2bfloat16(vr - __bfloat162float(h));
            h = __float2bfloat16(vi);
            g_kih[o] = h;
            g_kil[o] = __float2bfloat16(vi - __bfloat162float(h));
        }
    } else {
        for (int idx = tid; idx < 128 * 128; idx += 256) {
            int c = idx >> 7, f = idx & 127;
            float vr = s0[c * 133 + f];
            float vi = s1[c * 133 + f];
            if (f0 == 0 && f == 0) vr += SQRTN * __ldg(&bV[c]);
            size_t o = ((size_t)b * CH + c) * FT + f0 + f;
            __nv_bfloat16 h = __float2bfloat16(vr);
            g_vrh[o] = h;
            g_vrl[o] = __float2bfloat16(vr - __bfloat162float(h));
            h = __float2bfloat16(vi);
            g_vih[o] = h;
            g_vil[o] = __float2bfloat16(vi - __bfloat162float(h));
        }
    }
    __syncthreads();
    if (tid == 0) MBAR_INVAL(mbar);
    __syncthreads();
    if (wid == 0) tc_dealloc(tm, 256);
}

// ------- strip-mined QK: Q resident, K streamed, e = exp(|S|*scale) ----------
__global__ __launch_bounds__(256, 1) __cluster_dims__(1, 1, 1) void k_qk_mma() {
    extern __shared__ char sm[];
    uint32_t smb = smem_u32(sm);
    int tid = threadIdx.x, wid = tid >> 5, lane = tid & 31;
    int f0 = blockIdx.x * 128, b = blockIdx.y;

    if (wid == 0) tc_alloc(smb + R_QCTL, 512);
    if (tid == 0) MBAR_INIT(smb + R_QCTL + 8, 1);
    __syncthreads();
    uint32_t tm;
    asm volatile("ld.shared.b32 %0, [%1];" : "=r"(tm) : "r"(smb + R_QCTL));
    uint32_t mbar = smb + R_QCTL + 8;

    size_t qb = ((size_t)b * FT + f0) * CH;
    load_tile_pair_ca(smb, R_QR, g_qrh, g_qrl, qb, CH);
    load_tile_pair_ca(smb, R_QI, g_qih, g_qil, qb, CH);
    size_t kbase = (size_t)b * FT * CH;
    load_qk_bchunk(smb, kbase, 0);   // tile 0 kh 0 (commit covers Q loads too)

    uint32_t phase = 0;
    int half = wid >> 2, sp = wid & 3;
    int row = sp * 32 + lane;
    float rsum = 0.f;
    float* stg = (float*)(sm + R_STG);

#pragma unroll 1
    for (int t2 = 0; t2 < 17; t2++) {
        int g0 = t2 * 128;
        size_t kb = kbase + (size_t)g0 * CH;
#pragma unroll 1
        for (int kh = 0; kh < 2; kh++) {
            CP_WAIT0();
            FENCE_ASYNC();
            __syncthreads();
            if (wid == 0 && elect_one()) {
                qk_mma_khalf(tm, smb, kh);
                tc_commit(mbar);
            }
            mbar_wait(mbar, phase); phase ^= 1;
            // B region free: load kh1 of this tile, or prefetch next tile's kh0
            if (kh == 0) load_qk_bchunk(smb, kb, 1);
            else if (t2 < 16) load_qk_bchunk(smb, kb + (size_t)128 * CH, 0);
        }
        tc_fence_after();
        // epilogue (overlaps prefetch): each warp reads its subpartition rows,
        // cols split by warp half; stage 32-col strips for coalesced S stores.
        size_t sbase = ((size_t)b * FT + f0) * FT + g0;
#pragma unroll 1
        for (int cg = 0; cg < 64; cg += 32) {
            int col0 = half * 64 + cg;
            uint32_t ra[32], rb[32];
            tc_ld_x32(ra, tm + 0 + col0);
            tc_ld_x32(rb, tm + 256 + col0);
            tc_wait_ld();
            float srv[32];
#pragma unroll
            for (int c = 0; c < 32; c++) srv[c] = __uint_as_float(ra[c]) - __uint_as_float(rb[c]);
            tc_ld_x32(ra, tm + 128 + col0);
            tc_ld_x32(rb, tm + 384 + col0);
            tc_wait_ld();
            float* st = stg + half * 4224 + row * 33;
#pragma unroll
            for (int c = 0; c < 32; c++) {
                float si = __uint_as_float(ra[c]) + __uint_as_float(rb[c]);
                float sr = srv[c];
                float u = fmaxf(fmaf(sr, sr, si * si), 1e-30f);
                float y = __int_as_float(0x5f3759df - (__float_as_int(u) >> 1));
                float hu = 0.5f * u;
                y = y * (1.5f - hu * y * y);
                y = y * (1.5f - hu * y * y);
                float m = u * y;
                int gcol = g0 + col0 + c;
                float e = (gcol < NF) ? __expf(m * ATT_SCALE) : 0.f;
                rsum += e;
                st[c] = e;
            }
            __syncthreads();
            for (int idx = tid; idx < 8192; idx += 256) {
                int h2 = idx >> 12, r2 = (idx >> 5) & 127, c2 = idx & 31;
                g_S[sbase + (size_t)r2 * FT + h2 * 64 + cg + c2] = stg[h2 * 4224 + r2 * 33 + c2];
            }
            __syncthreads();
        }
        tc_fence_before();
        __syncthreads();
    }
    atomicAdd(&g_lsum[(size_t)b * FT + f0 + row], rsum);
    __syncthreads();
    if (tid == 0) MBAR_INVAL(mbar);
    __syncthreads();
    if (wid == 0) tc_dealloc(tm, 512);
}

// ---------------- O = P @ V via tcgen05; P built on-the-fly -------------------
__global__ __launch_bounds__(256, 1) __cluster_dims__(1, 1, 1) void k_av_mma() {
    extern __shared__ char sm[];
    __shared__ float invl_s[128];
    uint32_t smb = smem_u32(sm);
    int tid = threadIdx.x, wid = tid >> 5, lane = tid & 31;
    int f0 = blockIdx.x * 128, b = blockIdx.y;
    if (wid == 0) tc_alloc(smb + R_CTRL, 256);
    if (tid == 0) MBAR_INIT(smb + R_CTRL + 8, 1);
    if (tid < 128) {
        float ls = g_lsum[(size_t)b * FT + f0 + tid];
        invl_s[tid] = (ls > 0.f) ? 1.0f / ls : 0.f;
    }
    __syncthreads();
    uint32_t tm;
    asm volatile("ld.shared.b32 %0, [%1];" : "=r"(tm) : "r"(smb + R_CTRL));
    uint32_t mbar = smb + R_CTRL + 8;
    uint32_t phase = 0;
    for (int kt = 0; kt < 17; kt++) {
        int g0 = kt * 128;
        size_t vb = ((size_t)b * CH) * FT + g0;
        load_tile_pair_ca(smb, R_B0, g_vrh, g_vrl, vb, FT);
        load_tile_pair_ca(smb, R_B1, g_vih, g_vil, vb, FT);
        CP_COMMIT();
#pragma unroll
        for (int i = 0; i < 8; i++) {
            int chunk = tid + i * 256;
            int row = chunk >> 4, c8 = (chunk & 15) * 8;
            const float* srow = g_S + ((size_t)b * FT + f0 + row) * FT + g0 + c8;
            float4 ea = *(const float4*)srow;
            float4 eb = *(const float4*)(srow + 4);
            float iv = invl_s[row];
            float pv[8] = {ea.x * iv, ea.y * iv, ea.z * iv, ea.w * iv,
                           eb.x * iv, eb.y * iv, eb.z * iv, eb.w * iv};
            uint32_t hiw[4], low[4];
#pragma unroll
            for (int j = 0; j < 4; j++) {
                __nv_bfloat162 h2 = __floats2bfloat162_rn(pv[2 * j], pv[2 * j + 1]);
                hiw[j] = *(uint32_t*)&h2;
                float l0 = pv[2 * j]     - __bfloat162float(__low2bfloat16(h2));
                float l1 = pv[2 * j + 1] - __bfloat162float(__high2bfloat16(h2));
                __nv_bfloat162 l2 = __floats2bfloat162_rn(l0, l1);
                low[j] = *(uint32_t*)&l2;
            }
            int kh = c8 >> 6;
            uint32_t off = (uint32_t)(row * 128 + (c8 & 63) * 2);
            off ^= (off >> 3) & 0x70;
            *(uint4*)(sm + R_A + kh * 16384 + off)       = make_uint4(hiw[0], hiw[1], hiw[2], hiw[3]);
            *(uint4*)(sm + R_A + (2 + kh) * 16384 + off) = make_uint4(low[0], low[1], low[2], low[3]);
        }
        CP_WAIT0();
        FENCE_ASYNC();
        __syncthreads();
        if (wid == 0 && elect_one()) {
            mma_pair(tm, smb, R_A, R_B0, kt == 0);
            mma_pair(tm + 128, smb, R_A, R_B1, kt == 0);
            tc_commit(mbar);
        }
        mbar_wait(mbar, phase); phase ^= 1;
    }
    tc_fence_after();
    {
        int half = wid >> 2, w4 = wid & 3;
        float* stage = (float*)(sm + (half ? STAGE1 : STAGE0));
        uint32_t dbase = tm + half * 128;
        int row = w4 * 32 + lane;
#pragma unroll
        for (int part = 0; part < 4; part++) {
            uint32_t r[32];
            tc_ld_x32(r, dbase + part * 32);
            tc_wait_ld();
#pragma unroll
            for (int c = 0; c < 32; c++) stage[row * 132 + part * 32 + c] = __uint_as_float(r[c]);
        }
    }
    __syncthreads();
    {
        const float* str = (const float*)(sm + STAGE0);
        const float* sti = (const float*)(sm + STAGE1);
        for (int idx = tid; idx < 128 * 128; idx += 256) {
            int c = idx >> 7, fl = idx & 127;
            int gf = f0 + fl;
            if (gf < NF) {
                size_t o = ((size_t)b * CH + c) * FPAD + gf;
                g_Or[o] = str[fl * 132 + c];
                g_Oi[o] = sti[fl * 132 + c];
            }
        }
    }
    __syncthreads();
    if (tid == 0) MBAR_INVAL(mbar);
    __syncthreads();
    if (wid == 0) tc_dealloc(tm, 256);
}

// ---------------- median (exact radix select per batch) -----------------------
__global__ __launch_bounds__(256) void k_median() {
    __shared__ uint32_t sv[NF];
    __shared__ uint32_t hist[256];
    __shared__ int sh[2];
    int b = blockIdx.x;
    for (int i = threadIdx.x; i < NF; i += 256) sv[i] = __float_as_uint(g_energy[b * NF + i]);
    __syncthreads();
    float m = radix_select_smem(sv, NF, NF / 2, hist, sh, 256);
    if (threadIdx.x == 0) g_med[b] = m;
}

// ------- global quantile (fused normalize; exact radix select) ----------------
#define QSEL_N (BATCH * NF)
#define QSEL_SMEM ((QSEL_N + 256 + 2) * 4)
__global__ __launch_bounds__(512) void k_quantile(const float* __restrict__ qparam) {
    extern __shared__ uint32_t qsm[];
    uint32_t* sv = qsm;
    uint32_t* hist = qsm + QSEL_N;
    int* sh = (int*)(hist + 256);
    for (int i = threadIdx.x; i < QSEL_N; i += 512) {
        int b = i / NF;
        float v = g_energy[i] / (g_med[b] + 1e-6f);
        g_normv[i] = v;
        sv[i] = __float_as_uint(v);
    }
    __syncthreads();
    float q = qparam[0];
    float pos = q * (float)(QSEL_N - 1);
    int lo = (int)floorf(pos);
    if (lo < 0) lo = 0;
    if (lo > QSEL_N - 2) lo = QSEL_N - 2;
    float frac = pos - (float)lo;
    float a = radix_select_smem(sv, QSEL_N, lo, hist, sh, 512);
    __syncthreads();
    float bb = radix_select_smem(sv, QSEL_N, lo + 1, hist, sh, 512);
    if (threadIdx.x == 0) g_thr[0] = a + (bb - a) * frac;
}

// ---------------- inverse rfft (fused hi-freq mask) -> output (B,C,N) ---------
__global__ __launch_bounds__(512) void k_ifft(float* __restrict__ out,
                                              const float* __restrict__ w_high) {
    extern __shared__ float2 sm2[];
    float2* A = sm2;
    float2* Bb = sm2 + 4096;
    float2* tws = sm2 + 8192;
    for (int i = threadIdx.x; i < 4096; i += 512) tws[i] = g_tw[i];
    int bc = blockIdx.x;
    int b = bc >> 7, c = bc & 127;
    float whr = w_high[c * 2], whi = w_high[c * 2 + 1];
    float thr = g_thr[0];
    size_t base = (size_t)bc * FPAD;
    for (int k = threadIdx.x; k < 4096; k += 512) {
        int kk = (k <= 2048) ? k : (4096 - k);
        float sgn = (k <= 2048) ? 1.f : -1.f;
        float oR = g_Or[base + kk];
        float oI = g_Oi[base + kk];
        if (g_normv[b * NF + kk] > thr) {
            float xr = g_Xr[base + kk], xi = g_Xi[base + kk];
            oR += xr * whr - xi * whi;
            oI += xr * whi + xi * whr;
        }
        A[k] = make_float2(oR, sgn * oI);
    }
    fft4096_r4<1>(A, Bb, tws);
    const float s = 1.0f / SQRTN;
    float* orow = out + (size_t)bc * NT;
    for (int n = threadIdx.x; n < 4096; n += 512) orow[n] = A[n].x * s;
}

// ---------------- launch -------------------------------------------------------
extern "C" void kernel_launch(void* const* d_in, const int* in_sizes, int n_in,
                              void* d_out, int out_size) {
    const float* x_in   = (const float*)d_in[0];
    const float* W_K    = (const float*)d_in[1];
    const float* b_K    = (const float*)d_in[2];
    const float* W_V    = (const float*)d_in[3];
    const float* b_V    = (const float*)d_in[4];
    const float* w_high = (const float*)d_in[5];
    const float* qparam = (const float*)d_in[6];
    float* out = (float*)d_out;

    cudaFuncSetAttribute(k_fft_fwd,  cudaFuncAttributeMaxDynamicSharedMemorySize, FFT_SMEM);
    cudaFuncSetAttribute(k_ifft,     cudaFuncAttributeMaxDynamicSharedMemorySize, FFT_SMEM);
    cudaFuncSetAttribute(k_kv_mma,   cudaFuncAttributeMaxDynamicSharedMemorySize, MMA_SMEM_BYTES);
    cudaFuncSetAttribute(k_qk_mma,   cudaFuncAttributeMaxDynamicSharedMemorySize, QK_SMEM_BYTES);
    cudaFuncSetAttribute(k_av_mma,   cudaFuncAttributeMaxDynamicSharedMemorySize, MMA_SMEM_BYTES);
    cudaFuncSetAttribute(k_quantile, cudaFuncAttributeMaxDynamicSharedMemorySize, QSEL_SMEM);

    k_init<<<1, 512>>>(W_K, W_V);
    k_fft_fwd<<<BATCH * CH, 512, FFT_SMEM>>>(x_in);
    k_conv_qk<<<dim3(34, 16, 2), 256>>>();
    k_kv_mma<<<dim3(17, 8, 2), 256, MMA_SMEM_BYTES>>>(b_K, b_V);
    k_qk_mma<<<dim3(17, 8), 256, QK_SMEM_BYTES>>>();
    k_av_mma<<<dim3(17, 8), 256, MMA_SMEM_BYTES>>>();
    k_median<<<BATCH, 256>>>();
    k_quantile<<<1, 512, QSEL_SMEM>>>(qparam);
    k_ifft<<<BATCH * CH, 512, FFT_SMEM>>>(out, w_high);
}